// round 1
// baseline (speedup 1.0000x reference)
#include <cuda_runtime.h>
#include <math.h>

// ---------------- device scratch (no allocations allowed) ----------------
__device__ float g_feat[64 * 128 * 128];     // enc output, [c][y][x]
__device__ float g_out2[64 * 512 * 512];     // pre-tail features, [c][y][x]
__device__ float g_pred[3 * 512 * 512];      // tail output, [o][y][x]
__device__ float g_off[16 * 2];              // per-phase offsets (ch0=x, ch1=y)
__device__ float g_A[16 * 8 * 64];           // per-phase effective compress  [ph][k][c]
__device__ float g_B[16 * 64 * 8];           // per-phase effective expand    [ph][c][k]

// ---------------- K1: enc conv3x3, pad=1, 3->64 channels ----------------
__global__ void enc_kernel(const float* __restrict__ inp,
                           const float* __restrict__ w,
                           const float* __restrict__ b) {
    int idx = blockIdx.x * 256 + threadIdx.x;       // o*16384 + y*128 + x
    int o = idx >> 14;
    int rem = idx & 16383;
    int y = rem >> 7;
    int x = rem & 127;
    float acc = __ldg(b + o);
#pragma unroll
    for (int ci = 0; ci < 3; ci++) {
        const float* ip = inp + ci * 16384;
        const float* wp = w + (o * 3 + ci) * 9;
#pragma unroll
        for (int ky = 0; ky < 3; ky++) {
            int yy = y + ky - 1;
            if (yy < 0 || yy > 127) continue;
#pragma unroll
            for (int kx = 0; kx < 3; kx++) {
                int xx = x + kx - 1;
                if (xx < 0 || xx > 127) continue;
                acc += __ldg(ip + yy * 128 + xx) * __ldg(wp + ky * 3 + kx);
            }
        }
    }
    g_feat[idx] = acc;
}

// ---------------- K2: per-phase MLP -> r, off, effective A/B ----------------
__global__ void phase_kernel(const float* __restrict__ w1, const float* __restrict__ b1,
                             const float* __restrict__ w2, const float* __restrict__ b2,
                             const float* __restrict__ rw, const float* __restrict__ rb,
                             const float* __restrict__ ow, const float* __restrict__ ob,
                             const float* __restrict__ wc, const float* __restrict__ we) {
    __shared__ float s1[64], s2[64], sr[4];
    int c = threadIdx.x;
    int ph = blockIdx.x;                 // ph = (y%4)*4 + (x%4)
    float chv = ((ph >> 2) + 0.5f) * 0.25f - 0.5f;   // coor_h (row phase)
    float cwv = ((ph & 3)  + 0.5f) * 0.25f - 0.5f;   // coor_w (col phase)
    // inp4 channels: [cs, cs, coor_h, coor_w], cs = 1/4
    float e1 = b1[c] + w1[c * 4 + 0] * 0.25f + w1[c * 4 + 1] * 0.25f
                     + w1[c * 4 + 2] * chv   + w1[c * 4 + 3] * cwv;
    s1[c] = fmaxf(e1, 0.f);
    __syncthreads();
    float e2 = b2[c];
    for (int d = 0; d < 64; d++) e2 += w2[c * 64 + d] * s1[d];
    s2[c] = fmaxf(e2, 0.f);
    __syncthreads();
    if (c < 4) {
        float z = rb[c];
        for (int d = 0; d < 64; d++) z += rw[c * 64 + d] * s2[d];
        float rv = 1.f / (1.f + expf(-z));
        sr[c] = rv;
    } else if (c < 6) {
        int o = c - 4;
        float z = ob[o];
        for (int d = 0; d < 64; d++) z += ow[o * 64 + d] * s2[d];
        g_off[ph * 2 + o] = z;
    }
    __syncthreads();
    float r0 = sr[0], r1 = sr[1], r2 = sr[2], r3 = sr[3];
    // wc layout [e][k][c] (e stride 512); we layout [e][c][k] (e stride 512)
    for (int t = c; t < 512; t += 64) {
        g_A[ph * 512 + t] = r0 * wc[t] + r1 * wc[512 + t] + r2 * wc[1024 + t] + r3 * wc[1536 + t];
        g_B[ph * 512 + t] = r0 * we[t] + r1 * we[512 + t] + r2 * we[1024 + t] + r3 * we[1536 + t];
    }
}

// ---------------- K3: fused bilinear sample + expert mixing ----------------
__global__ void __launch_bounds__(256) main_kernel() {
    // only 4 phases appear per row (x%4 varies, y%4 fixed) -> 16 KB shared
    __shared__ __align__(16) float sA[4 * 512];
    __shared__ __align__(16) float sB[4 * 512];
    __shared__ float sOff[8];
    int tid = threadIdx.x;
    int y = blockIdx.y;
    int j = y & 3;
    for (int i = tid; i < 2048; i += 256) {
        sA[i] = g_A[j * 2048 + i];      // (j*4+pi)*512 + t  ==  j*2048 + i
        sB[i] = g_B[j * 2048 + i];
    }
    if (tid < 8) sOff[tid] = g_off[j * 8 + tid];
    __syncthreads();

    int x = blockIdx.x * 256 + tid;
    int pi = x & 3;
    float offx = sOff[pi * 2 + 0];
    float offy = sOff[pi * 2 + 1];
    const float C2 = 2.0f / 127.0f;
    float gx = ((x + 0.5f) * 0.25f - 0.5f) * C2 - 1.0f + offx * C2;
    float gy = ((y + 0.5f) * 0.25f - 0.5f) * C2 - 1.0f + offy * C2;
    float px = (gx + 1.0f) * 63.5f;
    float py = (gy + 1.0f) * 63.5f;
    float fx = floorf(px), fy = floorf(py);
    float wx1 = px - fx, wx0 = 1.f - wx1;
    float wy1 = py - fy, wy0 = 1.f - wy1;
    int ix0 = (int)fx, iy0 = (int)fy, ix1 = ix0 + 1, iy1 = iy0 + 1;
    float mx0 = (ix0 >= 0 && ix0 < 128) ? 1.f : 0.f;
    float mx1 = (ix1 >= 0 && ix1 < 128) ? 1.f : 0.f;
    float my0 = (iy0 >= 0 && iy0 < 128) ? 1.f : 0.f;
    float my1 = (iy1 >= 0 && iy1 < 128) ? 1.f : 0.f;
    int cx0 = min(127, max(0, ix0)), cx1 = min(127, max(0, ix1));
    int cy0 = min(127, max(0, iy0)), cy1 = min(127, max(0, iy1));
    float w00 = wy0 * wx0 * my0 * mx0, w01 = wy0 * wx1 * my0 * mx1;
    float w10 = wy1 * wx0 * my1 * mx0, w11 = wy1 * wx1 * my1 * mx1;
    int o00 = cy0 * 128 + cx0, o01 = cy0 * 128 + cx1;
    int o10 = cy1 * 128 + cx0, o11 = cy1 * 128 + cx1;

    float fea[64];
#pragma unroll
    for (int c = 0; c < 64; c++) {
        const float* fc = g_feat + (c << 14);
        fea[c] = w00 * __ldg(fc + o00) + w01 * __ldg(fc + o01)
               + w10 * __ldg(fc + o10) + w11 * __ldg(fc + o11);
    }

    // mid = A[ph] @ fea   (8x64)
    const float4* Ap = (const float4*)(sA + pi * 512);
    float mid[8];
#pragma unroll
    for (int k = 0; k < 8; k++) {
        float s = 0.f;
#pragma unroll
        for (int q = 0; q < 16; q++) {
            float4 w4 = Ap[k * 16 + q];
            s += w4.x * fea[q * 4] + w4.y * fea[q * 4 + 1]
               + w4.z * fea[q * 4 + 2] + w4.w * fea[q * 4 + 3];
        }
        mid[k] = s;
    }

    // out2 = fea + B[ph] @ mid   (64x8)
    const float4* Bp = (const float4*)(sB + pi * 512);
    int base = y * 512 + x;
#pragma unroll
    for (int c = 0; c < 64; c++) {
        float4 a = Bp[c * 2], b = Bp[c * 2 + 1];
        float s = a.x * mid[0] + a.y * mid[1] + a.z * mid[2] + a.w * mid[3]
                + b.x * mid[4] + b.y * mid[5] + b.z * mid[6] + b.w * mid[7];
        g_out2[(c << 18) + base] = fea[c] + s;
    }
}

// ---------------- K4: tail conv3x3, pad=1, 64->3 channels ----------------
__global__ void __launch_bounds__(256) tail_kernel(const float* __restrict__ tw,
                                                   const float* __restrict__ tb) {
    __shared__ __align__(16) float sW[3 * 64 * 12];   // padded [o][c][12]
    int tid = threadIdx.x;
    for (int i = tid; i < 2304; i += 256) sW[i] = 0.f;
    __syncthreads();
    for (int i = tid; i < 1728; i += 256) {
        int o = i / 576, rem = i % 576, c = rem / 9, t = rem % 9;
        sW[(o * 64 + c) * 12 + t] = tw[i];
    }
    __syncthreads();

    int x = blockIdx.x * 256 + tid;
    int y = blockIdx.y;
    bool xm = x > 0, xp = x < 511, ym = y > 0, yp = y < 511;
    float a0 = tb[0], a1 = tb[1], a2 = tb[2];
    int base = (y << 9) + x;
#pragma unroll 4
    for (int c = 0; c < 64; c++) {
        const float* p = g_out2 + (c << 18) + base;
        float v0 = (ym && xm) ? __ldg(p - 513) : 0.f;
        float v1 = ym ? __ldg(p - 512) : 0.f;
        float v2 = (ym && xp) ? __ldg(p - 511) : 0.f;
        float v3 = xm ? __ldg(p - 1) : 0.f;
        float v4 = __ldg(p);
        float v5 = xp ? __ldg(p + 1) : 0.f;
        float v6 = (yp && xm) ? __ldg(p + 511) : 0.f;
        float v7 = yp ? __ldg(p + 512) : 0.f;
        float v8 = (yp && xp) ? __ldg(p + 513) : 0.f;
        const float4* q0 = (const float4*)(sW + c * 12);
        const float4* q1 = (const float4*)(sW + (64 + c) * 12);
        const float4* q2 = (const float4*)(sW + (128 + c) * 12);
        float4 w;
        w = q0[0]; a0 += w.x * v0 + w.y * v1 + w.z * v2 + w.w * v3;
        w = q0[1]; a0 += w.x * v4 + w.y * v5 + w.z * v6 + w.w * v7;
        w = q0[2]; a0 += w.x * v8;
        w = q1[0]; a1 += w.x * v0 + w.y * v1 + w.z * v2 + w.w * v3;
        w = q1[1]; a1 += w.x * v4 + w.y * v5 + w.z * v6 + w.w * v7;
        w = q1[2]; a1 += w.x * v8;
        w = q2[0]; a2 += w.x * v0 + w.y * v1 + w.z * v2 + w.w * v3;
        w = q2[1]; a2 += w.x * v4 + w.y * v5 + w.z * v6 + w.w * v7;
        w = q2[2]; a2 += w.x * v8;
    }
    g_pred[base] = a0;
    g_pred[262144 + base] = a1;
    g_pred[524288 + base] = a2;
}

// ---------------- K5: query gather ----------------
__global__ void gather_kernel(const float* __restrict__ coord,
                              const float* __restrict__ cell,
                              float* __restrict__ out) {
    int q = blockIdx.x * 256 + threadIdx.x;
    float cy = coord[q * 2 + 0], cx = coord[q * 2 + 1];
    float hy = cell[q * 2 + 0] * 0.5f, hx = cell[q * 2 + 1] * 0.5f;
    const float LO = -0.999999f, HI = 0.999999f;
    float gyq = fminf(fmaxf(cy - hy + 1e-6f, LO), HI);
    float gxq = fminf(fmaxf(cx - hx + 1e-6f, LO), HI);
    int xi = (int)rintf((gxq + 1.0f) * 0.5f * 511.0f);
    int yi = (int)rintf((gyq + 1.0f) * 0.5f * 511.0f);
    xi = min(511, max(0, xi));
    yi = min(511, max(0, yi));
    int p = (yi << 9) + xi;
    out[q * 3 + 0] = g_pred[p];
    out[q * 3 + 1] = g_pred[262144 + p];
    out[q * 3 + 2] = g_pred[524288 + p];
}

// ---------------- launch ----------------
extern "C" void kernel_launch(void* const* d_in, const int* in_sizes, int n_in,
                              void* d_out, int out_size) {
    const float* inp   = (const float*)d_in[0];
    const float* coord = (const float*)d_in[1];
    const float* cell  = (const float*)d_in[2];
    const float* enc_w = (const float*)d_in[3];
    const float* enc_b = (const float*)d_in[4];
    const float* w1    = (const float*)d_in[5];
    const float* b1    = (const float*)d_in[6];
    const float* w2    = (const float*)d_in[7];
    const float* b2    = (const float*)d_in[8];
    const float* rw    = (const float*)d_in[9];
    const float* rb    = (const float*)d_in[10];
    const float* ow    = (const float*)d_in[11];
    const float* ob    = (const float*)d_in[12];
    const float* tw    = (const float*)d_in[13];
    const float* tb    = (const float*)d_in[14];
    const float* wc    = (const float*)d_in[15];
    const float* we    = (const float*)d_in[16];
    float* out = (float*)d_out;

    enc_kernel<<<4096, 256>>>(inp, enc_w, enc_b);
    phase_kernel<<<16, 64>>>(w1, b1, w2, b2, rw, rb, ow, ob, wc, we);
    main_kernel<<<dim3(2, 512), 256>>>();
    tail_kernel<<<dim3(2, 512), 256>>>(tw, tb);
    gather_kernel<<<1024, 256>>>(coord, cell, out);
}

// round 4
// speedup vs baseline: 1.0853x; 1.0853x over previous
#include <cuda_runtime.h>
#include <math.h>

typedef unsigned long long ull;

// ---------------- f32x2 packed helpers (Blackwell) ----------------
__device__ __forceinline__ ull pk2(float lo, float hi) {
    ull r; asm("mov.b64 %0, {%1,%2};" : "=l"(r) : "f"(lo), "f"(hi)); return r;
}
__device__ __forceinline__ float2 upk2(ull v) {
    float2 r; asm("mov.b64 {%0,%1}, %2;" : "=f"(r.x), "=f"(r.y) : "l"(v)); return r;
}
__device__ __forceinline__ ull ffma2(ull a, ull b, ull c) {
    ull d; asm("fma.rn.f32x2 %0, %1, %2, %3;" : "=l"(d) : "l"(a), "l"(b), "l"(c)); return d;
}

// ---------------- device scratch ----------------
__device__ float2 g_feat2[32 * 128 * 128];    // enc output, [pair][y][x], pair=(2c,2c+1)
__device__ float2 g_out2[32 * 512 * 512];     // pre-tail features, [pair][y][x]
__device__ float  g_pred[3 * 512 * 512];      // tail output, [o][y][x]
__device__ float  g_off[16 * 2];              // per-phase offsets (ch0=x, ch1=y)
__device__ float  g_A[16 * 8 * 64];           // per-phase effective compress  [ph][k][c]
__device__ float  g_Bt[16 * 8 * 64];          // per-phase effective expand TRANSPOSED [ph][k][c]

// ---------------- K1: enc conv3x3, pad=1, 3->64 ch, channel-pair output ----------------
__global__ void enc_kernel(const float* __restrict__ inp,
                           const float* __restrict__ w,
                           const float* __restrict__ b) {
    int idx = blockIdx.x * 256 + threadIdx.x;       // pair*16384 + y*128 + x
    int pair = idx >> 14;
    int rem = idx & 16383;
    int y = rem >> 7;
    int x = rem & 127;
    int c0 = pair * 2, c1 = c0 + 1;
    float a0 = __ldg(b + c0);
    float a1 = __ldg(b + c1);
#pragma unroll
    for (int ci = 0; ci < 3; ci++) {
        const float* ip = inp + ci * 16384;
        const float* w0 = w + (c0 * 3 + ci) * 9;
        const float* w1 = w + (c1 * 3 + ci) * 9;
#pragma unroll
        for (int ky = 0; ky < 3; ky++) {
            int yy = y + ky - 1;
            if (yy < 0 || yy > 127) continue;
#pragma unroll
            for (int kx = 0; kx < 3; kx++) {
                int xx = x + kx - 1;
                if (xx < 0 || xx > 127) continue;
                float v = __ldg(ip + yy * 128 + xx);
                a0 += v * __ldg(w0 + ky * 3 + kx);
                a1 += v * __ldg(w1 + ky * 3 + kx);
            }
        }
    }
    g_feat2[idx] = make_float2(a0, a1);
}

// ---------------- K2: per-phase MLP -> off, effective A / B^T ----------------
__global__ void phase_kernel(const float* __restrict__ w1, const float* __restrict__ b1,
                             const float* __restrict__ w2, const float* __restrict__ b2,
                             const float* __restrict__ rw, const float* __restrict__ rb,
                             const float* __restrict__ ow, const float* __restrict__ ob,
                             const float* __restrict__ wc, const float* __restrict__ we) {
    __shared__ float s1[64], s2[64], sr[4];
    int c = threadIdx.x;
    int ph = blockIdx.x;                 // ph = (y%4)*4 + (x%4)
    float chv = ((ph >> 2) + 0.5f) * 0.25f - 0.5f;
    float cwv = ((ph & 3)  + 0.5f) * 0.25f - 0.5f;
    float e1 = b1[c] + w1[c * 4 + 0] * 0.25f + w1[c * 4 + 1] * 0.25f
                     + w1[c * 4 + 2] * chv   + w1[c * 4 + 3] * cwv;
    s1[c] = fmaxf(e1, 0.f);
    __syncthreads();
    float e2 = b2[c];
    for (int d = 0; d < 64; d++) e2 += w2[c * 64 + d] * s1[d];
    s2[c] = fmaxf(e2, 0.f);
    __syncthreads();
    if (c < 4) {
        float z = rb[c];
        for (int d = 0; d < 64; d++) z += rw[c * 64 + d] * s2[d];
        sr[c] = 1.f / (1.f + expf(-z));
    } else if (c < 6) {
        int o = c - 4;
        float z = ob[o];
        for (int d = 0; d < 64; d++) z += ow[o * 64 + d] * s2[d];
        g_off[ph * 2 + o] = z;
    }
    __syncthreads();
    float r0 = sr[0], r1 = sr[1], r2 = sr[2], r3 = sr[3];
    // wc layout [e][k][c]; we layout [e][c][k] (e stride 512)
    for (int t = c; t < 512; t += 64) {
        g_A[ph * 512 + t] = r0 * wc[t] + r1 * wc[512 + t] + r2 * wc[1024 + t] + r3 * wc[1536 + t];
        float bmix = r0 * we[t] + r1 * we[512 + t] + r2 * we[1024 + t] + r3 * we[1536 + t];
        int ch = t >> 3, k = t & 7;                    // we index t = ch*8 + k
        g_Bt[ph * 512 + k * 64 + ch] = bmix;           // transposed [k][c]
    }
}

// ---------------- K3: fused bilinear sample + expert mixing (f32x2) ----------------
__global__ void __launch_bounds__(256) main_kernel() {
    __shared__ __align__(16) float sA[4 * 512];   // [pi][k][c]
    __shared__ __align__(16) float sBt[4 * 512];  // [pi][k][c]
    __shared__ float sOff[8];
    int tid = threadIdx.x;
    int y = blockIdx.y;
    int j = y & 3;
    for (int i = tid; i < 2048; i += 256) {
        sA[i]  = g_A[j * 2048 + i];
        sBt[i] = g_Bt[j * 2048 + i];
    }
    if (tid < 8) sOff[tid] = g_off[j * 8 + tid];
    __syncthreads();

    int x = blockIdx.x * 256 + tid;
    int pi = x & 3;
    float offx = sOff[pi * 2 + 0];
    float offy = sOff[pi * 2 + 1];
    const float C2 = 2.0f / 127.0f;
    float gx = ((x + 0.5f) * 0.25f - 0.5f) * C2 - 1.0f + offx * C2;
    float gy = ((y + 0.5f) * 0.25f - 0.5f) * C2 - 1.0f + offy * C2;
    float px = (gx + 1.0f) * 63.5f;
    float py = (gy + 1.0f) * 63.5f;
    float fx = floorf(px), fy = floorf(py);
    float wx1 = px - fx, wx0 = 1.f - wx1;
    float wy1 = py - fy, wy0 = 1.f - wy1;
    int ix0 = (int)fx, iy0 = (int)fy, ix1 = ix0 + 1, iy1 = iy0 + 1;
    float mx0 = (ix0 >= 0 && ix0 < 128) ? 1.f : 0.f;
    float mx1 = (ix1 >= 0 && ix1 < 128) ? 1.f : 0.f;
    float my0 = (iy0 >= 0 && iy0 < 128) ? 1.f : 0.f;
    float my1 = (iy1 >= 0 && iy1 < 128) ? 1.f : 0.f;
    int cx0 = min(127, max(0, ix0)), cx1 = min(127, max(0, ix1));
    int cy0 = min(127, max(0, iy0)), cy1 = min(127, max(0, iy1));
    ull w00 = pk2(wy0 * wx0 * my0 * mx0, wy0 * wx0 * my0 * mx0);
    ull w01 = pk2(wy0 * wx1 * my0 * mx1, wy0 * wx1 * my0 * mx1);
    ull w10 = pk2(wy1 * wx0 * my1 * mx0, wy1 * wx0 * my1 * mx0);
    ull w11 = pk2(wy1 * wx1 * my1 * mx1, wy1 * wx1 * my1 * mx1);
    int o00 = cy0 * 128 + cx0, o01 = cy0 * 128 + cx1;
    int o10 = cy1 * 128 + cx0, o11 = cy1 * 128 + cx1;

    // bilinear gather: 4 LDG.64 + 4 FFMA2 per channel-pair
    ull fea2[32];
#pragma unroll
    for (int i = 0; i < 32; i++) {
        const ull* F = (const ull*)(g_feat2 + (i << 14));
        ull v00 = __ldg(F + o00), v01 = __ldg(F + o01);
        ull v10 = __ldg(F + o10), v11 = __ldg(F + o11);
        ull t = ffma2(w00, v00, 0ULL);
        t = ffma2(w01, v01, t);
        t = ffma2(w10, v10, t);
        fea2[i] = ffma2(w11, v11, t);
    }

    // mid = A[ph] @ fea  (8x64) — packed accumulate + horizontal add
    const ull* Ap = (const ull*)(sA + pi * 512);
    ull mid2[8];
#pragma unroll
    for (int k = 0; k < 8; k++) {
        ull acc = 0ULL;
#pragma unroll
        for (int i = 0; i < 32; i++) acc = ffma2(Ap[k * 32 + i], fea2[i], acc);
        float2 a = upk2(acc);
        float m = a.x + a.y;
        mid2[k] = pk2(m, m);
    }

    // out2 = fea + B^T[k][c] accumulated over k (in-place into fea2)
    const ull* Bp = (const ull*)(sBt + pi * 512);
#pragma unroll
    for (int k = 0; k < 8; k++) {
        ull mk = mid2[k];
#pragma unroll
        for (int i = 0; i < 32; i++) fea2[i] = ffma2(Bp[k * 32 + i], mk, fea2[i]);
    }

    int base = y * 512 + x;
#pragma unroll
    for (int i = 0; i < 32; i++) {
        float2 v = upk2(fea2[i]);
        g_out2[(i << 18) + base] = v;
    }
}

// ---------------- K4: tail conv3x3, 64->3 ch, f32x2 + 2-row reuse ----------------
__global__ void __launch_bounds__(256) tail_kernel(const float* __restrict__ tw,
                                                   const float* __restrict__ tb) {
    __shared__ __align__(16) ull sw2[3][32][9];     // packed (c0,c1) weights
    int tid = threadIdx.x;
    for (int i = tid; i < 864; i += 256) {
        int o = i / 288, rem = i % 288, p = rem / 9, t = rem % 9;
        sw2[o][p][t] = pk2(tw[o * 576 + (2 * p) * 9 + t],
                           tw[o * 576 + (2 * p + 1) * 9 + t]);
    }
    __syncthreads();

    int x = blockIdx.x * 256 + tid;
    int y0 = blockIdx.y * 2;
    bool xm = x > 0, xp = x < 511;
    ull acc[2][3];
#pragma unroll
    for (int oy = 0; oy < 2; oy++)
#pragma unroll
        for (int o = 0; o < 3; o++) acc[oy][o] = 0ULL;

    for (int pair = 0; pair < 32; pair++) {
        const ull* P = (const ull*)(g_out2 + (pair << 18));
        ull v[4][3];
#pragma unroll
        for (int r = 0; r < 4; r++) {
            int yy = y0 - 1 + r;
            bool vy = (yy >= 0) && (yy < 512);
            int row = yy * 512 + x;
            v[r][0] = (vy && xm) ? __ldg(P + row - 1) : 0ULL;
            v[r][1] = vy ? __ldg(P + row) : 0ULL;
            v[r][2] = (vy && xp) ? __ldg(P + row + 1) : 0ULL;
        }
#pragma unroll
        for (int oy = 0; oy < 2; oy++)
#pragma unroll
            for (int ky = 0; ky < 3; ky++)
#pragma unroll
                for (int kx = 0; kx < 3; kx++) {
                    ull vv = v[oy + ky][kx];
#pragma unroll
                    for (int o = 0; o < 3; o++)
                        acc[oy][o] = ffma2(sw2[o][pair][ky * 3 + kx], vv, acc[oy][o]);
                }
    }
#pragma unroll
    for (int oy = 0; oy < 2; oy++) {
        int row = (y0 + oy) * 512 + x;
#pragma unroll
        for (int o = 0; o < 3; o++) {
            float2 a = upk2(acc[oy][o]);
            g_pred[o * 262144 + row] = __ldg(tb + o) + a.x + a.y;
        }
    }
}

// ---------------- K5: query gather ----------------
__global__ void gather_kernel(const float* __restrict__ coord,
                              const float* __restrict__ cell,
                              float* __restrict__ out) {
    int q = blockIdx.x * 256 + threadIdx.x;
    float cy = coord[q * 2 + 0], cx = coord[q * 2 + 1];
    float hy = cell[q * 2 + 0] * 0.5f, hx = cell[q * 2 + 1] * 0.5f;
    const float LO = -0.999999f, HI = 0.999999f;
    float gyq = fminf(fmaxf(cy - hy + 1e-6f, LO), HI);
    float gxq = fminf(fmaxf(cx - hx + 1e-6f, LO), HI);
    int xi = (int)rintf((gxq + 1.0f) * 0.5f * 511.0f);
    int yi = (int)rintf((gyq + 1.0f) * 0.5f * 511.0f);
    xi = min(511, max(0, xi));
    yi = min(511, max(0, yi));
    int p = (yi << 9) + xi;
    out[q * 3 + 0] = g_pred[p];
    out[q * 3 + 1] = g_pred[262144 + p];
    out[q * 3 + 2] = g_pred[524288 + p];
}

// ---------------- launch ----------------
extern "C" void kernel_launch(void* const* d_in, const int* in_sizes, int n_in,
                              void* d_out, int out_size) {
    const float* inp   = (const float*)d_in[0];
    const float* coord = (const float*)d_in[1];
    const float* cell  = (const float*)d_in[2];
    const float* enc_w = (const float*)d_in[3];
    const float* enc_b = (const float*)d_in[4];
    const float* w1    = (const float*)d_in[5];
    const float* b1    = (const float*)d_in[6];
    const float* w2    = (const float*)d_in[7];
    const float* b2    = (const float*)d_in[8];
    const float* rw    = (const float*)d_in[9];
    const float* rb    = (const float*)d_in[10];
    const float* ow    = (const float*)d_in[11];
    const float* ob    = (const float*)d_in[12];
    const float* tw    = (const float*)d_in[13];
    const float* tb    = (const float*)d_in[14];
    const float* wc    = (const float*)d_in[15];
    const float* we    = (const float*)d_in[16];
    float* out = (float*)d_out;

    enc_kernel<<<2048, 256>>>(inp, enc_w, enc_b);
    phase_kernel<<<16, 64>>>(w1, b1, w2, b2, rw, rb, ow, ob, wc, we);
    main_kernel<<<dim3(2, 512), 256>>>();
    tail_kernel<<<dim3(2, 256), 256>>>(tw, tb);
    gather_kernel<<<1024, 256>>>(coord, cell, out);
}

// round 5
// speedup vs baseline: 1.1828x; 1.0898x over previous
#include <cuda_runtime.h>
#include <math.h>

typedef unsigned long long ull;

// ---------------- f32x2 packed helpers (Blackwell) ----------------
__device__ __forceinline__ ull pk2(float lo, float hi) {
    ull r; asm("mov.b64 %0, {%1,%2};" : "=l"(r) : "f"(lo), "f"(hi)); return r;
}
__device__ __forceinline__ float2 upk2(ull v) {
    float2 r; asm("mov.b64 {%0,%1}, %2;" : "=f"(r.x), "=f"(r.y) : "l"(v)); return r;
}
__device__ __forceinline__ ull ffma2(ull a, ull b, ull c) {
    ull d; asm("fma.rn.f32x2 %0, %1, %2, %3;" : "=l"(d) : "l"(a), "l"(b), "l"(c)); return d;
}

// ---------------- device scratch ----------------
__device__ float2 g_feat2[32 * 128 * 128];    // enc output, [pair][y][x]
__device__ float2 g_out2[32 * 512 * 512];     // pre-tail features, [pair][y][x]
__device__ float  g_pred[3 * 512 * 512];      // tail output, [o][y][x]
__device__ float  g_off[16 * 2];              // per-phase offsets (ch0=x, ch1=y)
__device__ float  g_A[16 * 8 * 64];           // per-phase compress  [ph][k][c]
__device__ float  g_B[16 * 64 * 8];           // per-phase expand    [ph][c][k]
__device__ ull    g_AF2[16 * 4 * 16384];      // A_ph @ feat, [ph][kpair][pos], packed k-pairs

// ---------------- K1: enc conv3x3, pad=1, 3->64 ch ----------------
__global__ void enc_kernel(const float* __restrict__ inp,
                           const float* __restrict__ w,
                           const float* __restrict__ b) {
    int idx = blockIdx.x * 256 + threadIdx.x;       // pair*16384 + y*128 + x
    int pair = idx >> 14;
    int rem = idx & 16383;
    int y = rem >> 7;
    int x = rem & 127;
    int c0 = pair * 2, c1 = c0 + 1;
    float a0 = __ldg(b + c0);
    float a1 = __ldg(b + c1);
#pragma unroll
    for (int ci = 0; ci < 3; ci++) {
        const float* ip = inp + ci * 16384;
        const float* w0 = w + (c0 * 3 + ci) * 9;
        const float* w1 = w + (c1 * 3 + ci) * 9;
#pragma unroll
        for (int ky = 0; ky < 3; ky++) {
            int yy = y + ky - 1;
            if (yy < 0 || yy > 127) continue;
#pragma unroll
            for (int kx = 0; kx < 3; kx++) {
                int xx = x + kx - 1;
                if (xx < 0 || xx > 127) continue;
                float v = __ldg(ip + yy * 128 + xx);
                a0 += v * __ldg(w0 + ky * 3 + kx);
                a1 += v * __ldg(w1 + ky * 3 + kx);
            }
        }
    }
    g_feat2[idx] = make_float2(a0, a1);
}

// ---------------- K2: per-phase MLP -> off, A, B ----------------
__global__ void phase_kernel(const float* __restrict__ w1, const float* __restrict__ b1,
                             const float* __restrict__ w2, const float* __restrict__ b2,
                             const float* __restrict__ rw, const float* __restrict__ rb,
                             const float* __restrict__ ow, const float* __restrict__ ob,
                             const float* __restrict__ wc, const float* __restrict__ we) {
    __shared__ float s1[64], s2[64], sr[4];
    int c = threadIdx.x;
    int ph = blockIdx.x;                 // ph = (y%4)*4 + (x%4)
    float chv = ((ph >> 2) + 0.5f) * 0.25f - 0.5f;
    float cwv = ((ph & 3)  + 0.5f) * 0.25f - 0.5f;
    float e1 = b1[c] + w1[c * 4 + 0] * 0.25f + w1[c * 4 + 1] * 0.25f
                     + w1[c * 4 + 2] * chv   + w1[c * 4 + 3] * cwv;
    s1[c] = fmaxf(e1, 0.f);
    __syncthreads();
    float e2 = b2[c];
    for (int d = 0; d < 64; d++) e2 += w2[c * 64 + d] * s1[d];
    s2[c] = fmaxf(e2, 0.f);
    __syncthreads();
    if (c < 4) {
        float z = rb[c];
        for (int d = 0; d < 64; d++) z += rw[c * 64 + d] * s2[d];
        sr[c] = 1.f / (1.f + expf(-z));
    } else if (c < 6) {
        int o = c - 4;
        float z = ob[o];
        for (int d = 0; d < 64; d++) z += ow[o * 64 + d] * s2[d];
        g_off[ph * 2 + o] = z;
    }
    __syncthreads();
    float r0 = sr[0], r1 = sr[1], r2 = sr[2], r3 = sr[3];
    // wc layout [e][k][c]; we layout [e][c][k] (e stride 512)
    for (int t = c; t < 512; t += 64) {
        g_A[ph * 512 + t] = r0 * wc[t] + r1 * wc[512 + t] + r2 * wc[1024 + t] + r3 * wc[1536 + t];
        g_B[ph * 512 + t] = r0 * we[t] + r1 * we[512 + t] + r2 * we[1024 + t] + r3 * we[1536 + t];
    }
}

// ---------------- K2b: AF[ph][k][pos] = A_ph @ feat(:,pos) ----------------
__global__ void __launch_bounds__(256) af_kernel() {
    __shared__ ull sA2[256];                 // [k][cpair] for this phase
    int tid = threadIdx.x;
    int ph = blockIdx.x >> 6;                // 16 phases x 64 chunks
    int chunk = blockIdx.x & 63;
    if (tid < 256) sA2[tid] = ((const ull*)g_A)[ph * 256 + tid];
    __syncthreads();
    int pos = chunk * 256 + tid;

    ull f2[32];
#pragma unroll
    for (int i = 0; i < 32; i++)
        f2[i] = __ldg((const ull*)g_feat2 + (i << 14) + pos);

    float m[8];
#pragma unroll
    for (int k = 0; k < 8; k++) {
        ull acc = 0ULL;
#pragma unroll
        for (int i = 0; i < 32; i++) acc = ffma2(sA2[k * 32 + i], f2[i], acc);
        float2 a = upk2(acc);
        m[k] = a.x + a.y;
    }
#pragma unroll
    for (int kp = 0; kp < 4; kp++)
        g_AF2[(ph * 4 + kp) * 16384 + pos] = pk2(m[2 * kp], m[2 * kp + 1]);
}

// ---------------- K3: streaming bilinear + low-rank mix ----------------
__global__ void __launch_bounds__(256) main_kernel() {
    __shared__ ull sB2[4][32][8];            // [pi][cpair][k] packed over channel pair
    __shared__ float sOff[8];
    int tid = threadIdx.x;
    int y = blockIdx.y;
    int j = y & 3;
    for (int t = tid; t < 1024; t += 256) {
        int pi = t >> 8, rem = t & 255, i = rem >> 3, k = rem & 7;
        const float* Bp = g_B + (j * 4 + pi) * 512;
        sB2[pi][i][k] = pk2(Bp[(2 * i) * 8 + k], Bp[(2 * i + 1) * 8 + k]);
    }
    if (tid < 8) sOff[tid] = g_off[j * 8 + tid];
    __syncthreads();

    int x = blockIdx.x * 256 + tid;
    int pi = x & 3;
    int ph = j * 4 + pi;
    float offx = sOff[pi * 2 + 0];
    float offy = sOff[pi * 2 + 1];
    const float C2 = 2.0f / 127.0f;
    float gx = ((x + 0.5f) * 0.25f - 0.5f) * C2 - 1.0f + offx * C2;
    float gy = ((y + 0.5f) * 0.25f - 0.5f) * C2 - 1.0f + offy * C2;
    float px = (gx + 1.0f) * 63.5f;
    float py = (gy + 1.0f) * 63.5f;
    float fx = floorf(px), fy = floorf(py);
    float wx1 = px - fx, wx0 = 1.f - wx1;
    float wy1 = py - fy, wy0 = 1.f - wy1;
    int ix0 = (int)fx, iy0 = (int)fy, ix1 = ix0 + 1, iy1 = iy0 + 1;
    float mx0 = (ix0 >= 0 && ix0 < 128) ? 1.f : 0.f;
    float mx1 = (ix1 >= 0 && ix1 < 128) ? 1.f : 0.f;
    float my0 = (iy0 >= 0 && iy0 < 128) ? 1.f : 0.f;
    float my1 = (iy1 >= 0 && iy1 < 128) ? 1.f : 0.f;
    int cx0 = min(127, max(0, ix0)), cx1 = min(127, max(0, ix1));
    int cy0 = min(127, max(0, iy0)), cy1 = min(127, max(0, iy1));
    float f00 = wy0 * wx0 * my0 * mx0, f01 = wy0 * wx1 * my0 * mx1;
    float f10 = wy1 * wx0 * my1 * mx0, f11 = wy1 * wx1 * my1 * mx1;
    ull w00 = pk2(f00, f00), w01 = pk2(f01, f01);
    ull w10 = pk2(f10, f10), w11 = pk2(f11, f11);
    int o00 = cy0 * 128 + cx0, o01 = cy0 * 128 + cx1;
    int o10 = cy1 * 128 + cx0, o11 = cy1 * 128 + cx1;

    // mid via bilinear of AF (16 LDG.64 + 16 FFMA2)
    ull mk[8];
    const ull* AFp = g_AF2 + ph * 4 * 16384;
#pragma unroll
    for (int kp = 0; kp < 4; kp++) {
        const ull* Q = AFp + kp * 16384;
        ull a = ffma2(w00, __ldg(Q + o00), 0ULL);
        a = ffma2(w01, __ldg(Q + o01), a);
        a = ffma2(w10, __ldg(Q + o10), a);
        a = ffma2(w11, __ldg(Q + o11), a);
        float2 mm = upk2(a);
        mk[2 * kp]     = pk2(mm.x, mm.x);
        mk[2 * kp + 1] = pk2(mm.y, mm.y);
    }

    // stream channel pairs: gather + inline B accumulation + store
    int base = y * 512 + x;
#pragma unroll
    for (int i = 0; i < 32; i++) {
        const ull* F = (const ull*)g_feat2 + (i << 14);
        ull t = ffma2(w00, __ldg(F + o00), 0ULL);
        t = ffma2(w01, __ldg(F + o01), t);
        t = ffma2(w10, __ldg(F + o10), t);
        t = ffma2(w11, __ldg(F + o11), t);
#pragma unroll
        for (int k = 0; k < 8; k++) t = ffma2(sB2[pi][i][k], mk[k], t);
        ((ull*)g_out2)[(i << 18) + base] = t;
    }
}

// ---------------- K4: tail conv3x3, 64->3 ch, 4-row streaming ----------------
__global__ void __launch_bounds__(256) tail_kernel(const float* __restrict__ tw,
                                                   const float* __restrict__ tb) {
    __shared__ __align__(16) ull sw2[3][32][9];     // packed (c0,c1) weights
    int tid = threadIdx.x;
    for (int i = tid; i < 864; i += 256) {
        int o = i / 288, rem = i % 288, p = rem / 9, t = rem % 9;
        sw2[o][p][t] = pk2(tw[o * 576 + (2 * p) * 9 + t],
                           tw[o * 576 + (2 * p + 1) * 9 + t]);
    }
    __syncthreads();

    int x = blockIdx.x * 256 + tid;
    int y0 = blockIdx.y * 4;
    bool xm = x > 0, xp = x < 511;
    ull acc[4][3];
#pragma unroll
    for (int oy = 0; oy < 4; oy++)
#pragma unroll
        for (int o = 0; o < 3; o++) acc[oy][o] = 0ULL;

    for (int pair = 0; pair < 32; pair++) {
        const ull* P = (const ull*)g_out2 + (pair << 18);
#pragma unroll
        for (int r = 0; r < 6; r++) {
            int yy = y0 - 1 + r;
            bool vy = (yy >= 0) && (yy < 512);
            int row = yy * 512 + x;
            ull v0 = (vy && xm) ? __ldg(P + row - 1) : 0ULL;
            ull v1 = vy ? __ldg(P + row) : 0ULL;
            ull v2 = (vy && xp) ? __ldg(P + row + 1) : 0ULL;
#pragma unroll
            for (int oy = 0; oy < 4; oy++) {
                int ky = r - oy;
                if (ky < 0 || ky > 2) continue;
#pragma unroll
                for (int o = 0; o < 3; o++) {
                    ull a = acc[oy][o];
                    a = ffma2(sw2[o][pair][ky * 3 + 0], v0, a);
                    a = ffma2(sw2[o][pair][ky * 3 + 1], v1, a);
                    a = ffma2(sw2[o][pair][ky * 3 + 2], v2, a);
                    acc[oy][o] = a;
                }
            }
        }
    }
#pragma unroll
    for (int oy = 0; oy < 4; oy++) {
        int row = (y0 + oy) * 512 + x;
#pragma unroll
        for (int o = 0; o < 3; o++) {
            float2 a = upk2(acc[oy][o]);
            g_pred[o * 262144 + row] = __ldg(tb + o) + a.x + a.y;
        }
    }
}

// ---------------- K5: query gather ----------------
__global__ void gather_kernel(const float* __restrict__ coord,
                              const float* __restrict__ cell,
                              float* __restrict__ out) {
    int q = blockIdx.x * 256 + threadIdx.x;
    float2 cd = __ldg((const float2*)coord + q);
    float2 cl = __ldg((const float2*)cell + q);
    const float LO = -0.999999f, HI = 0.999999f;
    float gyq = fminf(fmaxf(cd.x - cl.x * 0.5f + 1e-6f, LO), HI);
    float gxq = fminf(fmaxf(cd.y - cl.y * 0.5f + 1e-6f, LO), HI);
    int xi = (int)rintf((gxq + 1.0f) * 0.5f * 511.0f);
    int yi = (int)rintf((gyq + 1.0f) * 0.5f * 511.0f);
    xi = min(511, max(0, xi));
    yi = min(511, max(0, yi));
    int p = (yi << 9) + xi;
    out[q * 3 + 0] = g_pred[p];
    out[q * 3 + 1] = g_pred[262144 + p];
    out[q * 3 + 2] = g_pred[524288 + p];
}

// ---------------- launch ----------------
extern "C" void kernel_launch(void* const* d_in, const int* in_sizes, int n_in,
                              void* d_out, int out_size) {
    const float* inp   = (const float*)d_in[0];
    const float* coord = (const float*)d_in[1];
    const float* cell  = (const float*)d_in[2];
    const float* enc_w = (const float*)d_in[3];
    const float* enc_b = (const float*)d_in[4];
    const float* w1    = (const float*)d_in[5];
    const float* b1    = (const float*)d_in[6];
    const float* w2    = (const float*)d_in[7];
    const float* b2    = (const float*)d_in[8];
    const float* rw    = (const float*)d_in[9];
    const float* rb    = (const float*)d_in[10];
    const float* ow    = (const float*)d_in[11];
    const float* ob    = (const float*)d_in[12];
    const float* tw    = (const float*)d_in[13];
    const float* tb    = (const float*)d_in[14];
    const float* wc    = (const float*)d_in[15];
    const float* we    = (const float*)d_in[16];
    float* out = (float*)d_out;

    enc_kernel<<<2048, 256>>>(inp, enc_w, enc_b);
    phase_kernel<<<16, 64>>>(w1, b1, w2, b2, rw, rb, ow, ob, wc, we);
    af_kernel<<<1024, 256>>>();
    main_kernel<<<dim3(2, 512), 256>>>();
    tail_kernel<<<dim3(2, 128), 256>>>(tw, tb);
    gather_kernel<<<1024, 256>>>(coord, cell, out);
}

// round 6
// speedup vs baseline: 1.5125x; 1.2788x over previous
#include <cuda_runtime.h>
#include <math.h>

typedef unsigned long long ull;

// ---------------- f32x2 packed helpers (Blackwell) ----------------
__device__ __forceinline__ ull pk2(float lo, float hi) {
    ull r; asm("mov.b64 %0, {%1,%2};" : "=l"(r) : "f"(lo), "f"(hi)); return r;
}
__device__ __forceinline__ float2 upk2(ull v) {
    float2 r; asm("mov.b64 {%0,%1}, %2;" : "=f"(r.x), "=f"(r.y) : "l"(v)); return r;
}
__device__ __forceinline__ ull ffma2(ull a, ull b, ull c) {
    ull d; asm("fma.rn.f32x2 %0, %1, %2, %3;" : "=l"(d) : "l"(a), "l"(b), "l"(c)); return d;
}

// ---------------- device scratch ----------------
__device__ float2 g_feat2[32 * 128 * 128];    // enc output, [pair][y][x]
__device__ float2 g_out2[32 * 512 * 512];     // pre-tail features, [pair][y][x]
__device__ float4 g_pred4[512 * 512];         // tail output, [y][x] -> (r,g,b,_)
__device__ float  g_off[16 * 2];              // per-phase offsets (ch0=x, ch1=y)
__device__ float  g_A[16 * 8 * 64];           // per-phase compress  [ph][k][c]
__device__ float  g_B[16 * 64 * 8];           // per-phase expand    [ph][c][k]
__device__ ull    g_AF2[16 * 4 * 16384];      // A_ph @ feat, [ph][kpair][pos]

// ---------------- K1: enc conv3x3, pad=1, 3->64 ch ----------------
__global__ void __launch_bounds__(256) enc_kernel(const float* __restrict__ inp,
                                                  const float* __restrict__ w,
                                                  const float* __restrict__ b) {
    __shared__ float sw[54];
    __shared__ float sb[2];
    int idx = blockIdx.x * 256 + threadIdx.x;       // pair*16384 + y*128 + x
    int pair = idx >> 14;                            // constant per block
    if (threadIdx.x < 54) sw[threadIdx.x] = w[pair * 54 + threadIdx.x];
    if (threadIdx.x < 2)  sb[threadIdx.x] = b[pair * 2 + threadIdx.x];
    __syncthreads();
    int rem = idx & 16383;
    int y = rem >> 7;
    int x = rem & 127;
    float a0 = sb[0], a1 = sb[1];
#pragma unroll
    for (int ci = 0; ci < 3; ci++) {
        const float* ip = inp + ci * 16384;
        const float* w0 = sw + ci * 9;
        const float* w1 = sw + 27 + ci * 9;
#pragma unroll
        for (int ky = 0; ky < 3; ky++) {
            int yy = y + ky - 1;
            if (yy < 0 || yy > 127) continue;
#pragma unroll
            for (int kx = 0; kx < 3; kx++) {
                int xx = x + kx - 1;
                if (xx < 0 || xx > 127) continue;
                float v = __ldg(ip + yy * 128 + xx);
                a0 += v * w0[ky * 3 + kx];
                a1 += v * w1[ky * 3 + kx];
            }
        }
    }
    g_feat2[idx] = make_float2(a0, a1);
}

// ---------------- K2: per-phase MLP -> off, A, B ----------------
__global__ void phase_kernel(const float* __restrict__ w1, const float* __restrict__ b1,
                             const float* __restrict__ w2, const float* __restrict__ b2,
                             const float* __restrict__ rw, const float* __restrict__ rb,
                             const float* __restrict__ ow, const float* __restrict__ ob,
                             const float* __restrict__ wc, const float* __restrict__ we) {
    __shared__ float s1[64], s2[64], sr[4];
    int c = threadIdx.x;
    int ph = blockIdx.x;                 // ph = (y%4)*4 + (x%4)
    float chv = ((ph >> 2) + 0.5f) * 0.25f - 0.5f;
    float cwv = ((ph & 3)  + 0.5f) * 0.25f - 0.5f;
    float e1 = b1[c] + w1[c * 4 + 0] * 0.25f + w1[c * 4 + 1] * 0.25f
                     + w1[c * 4 + 2] * chv   + w1[c * 4 + 3] * cwv;
    s1[c] = fmaxf(e1, 0.f);
    __syncthreads();
    float e2 = b2[c];
    for (int d = 0; d < 64; d++) e2 += w2[c * 64 + d] * s1[d];
    s2[c] = fmaxf(e2, 0.f);
    __syncthreads();
    if (c < 4) {
        float z = rb[c];
        for (int d = 0; d < 64; d++) z += rw[c * 64 + d] * s2[d];
        sr[c] = 1.f / (1.f + expf(-z));
    } else if (c < 6) {
        int o = c - 4;
        float z = ob[o];
        for (int d = 0; d < 64; d++) z += ow[o * 64 + d] * s2[d];
        g_off[ph * 2 + o] = z;
    }
    __syncthreads();
    float r0 = sr[0], r1 = sr[1], r2 = sr[2], r3 = sr[3];
    for (int t = c; t < 512; t += 64) {
        g_A[ph * 512 + t] = r0 * wc[t] + r1 * wc[512 + t] + r2 * wc[1024 + t] + r3 * wc[1536 + t];
        g_B[ph * 512 + t] = r0 * we[t] + r1 * we[512 + t] + r2 * we[1024 + t] + r3 * we[1536 + t];
    }
}

// ---------------- K2b: AF[ph][k][pos] = A_ph @ feat(:,pos) ----------------
__global__ void __launch_bounds__(256) af_kernel() {
    __shared__ ull sA2[256];                 // [k][cpair] for this phase
    int tid = threadIdx.x;
    int ph = blockIdx.x >> 6;                // 16 phases x 64 chunks
    int chunk = blockIdx.x & 63;
    if (tid < 256) sA2[tid] = ((const ull*)g_A)[ph * 256 + tid];
    __syncthreads();
    int pos = chunk * 256 + tid;

    ull f2[32];
#pragma unroll
    for (int i = 0; i < 32; i++)
        f2[i] = __ldg((const ull*)g_feat2 + (i << 14) + pos);

    float m[8];
#pragma unroll
    for (int k = 0; k < 8; k++) {
        ull acc = 0ULL;
#pragma unroll
        for (int i = 0; i < 32; i++) acc = ffma2(sA2[k * 32 + i], f2[i], acc);
        float2 a = upk2(acc);
        m[k] = a.x + a.y;
    }
#pragma unroll
    for (int kp = 0; kp < 4; kp++)
        g_AF2[(ph * 4 + kp) * 16384 + pos] = pk2(m[2 * kp], m[2 * kp + 1]);
}

// ---------------- bilinear coordinate pack ----------------
struct Bil {
    ull w00, w01, w10, w11;
    int o00, o01, o10, o11;
};
__device__ __forceinline__ Bil make_bil(int x, int y, float offx, float offy) {
    Bil r;
    const float C2 = 2.0f / 127.0f;
    float gx = ((x + 0.5f) * 0.25f - 0.5f) * C2 - 1.0f + offx * C2;
    float gy = ((y + 0.5f) * 0.25f - 0.5f) * C2 - 1.0f + offy * C2;
    float px = (gx + 1.0f) * 63.5f;
    float py = (gy + 1.0f) * 63.5f;
    float fx = floorf(px), fy = floorf(py);
    float wx1 = px - fx, wx0 = 1.f - wx1;
    float wy1 = py - fy, wy0 = 1.f - wy1;
    int ix0 = (int)fx, iy0 = (int)fy, ix1 = ix0 + 1, iy1 = iy0 + 1;
    float mx0 = (ix0 >= 0 && ix0 < 128) ? 1.f : 0.f;
    float mx1 = (ix1 >= 0 && ix1 < 128) ? 1.f : 0.f;
    float my0 = (iy0 >= 0 && iy0 < 128) ? 1.f : 0.f;
    float my1 = (iy1 >= 0 && iy1 < 128) ? 1.f : 0.f;
    int cx0 = min(127, max(0, ix0)), cx1 = min(127, max(0, ix1));
    int cy0 = min(127, max(0, iy0)), cy1 = min(127, max(0, iy1));
    float f00 = wy0 * wx0 * my0 * mx0, f01 = wy0 * wx1 * my0 * mx1;
    float f10 = wy1 * wx0 * my1 * mx0, f11 = wy1 * wx1 * my1 * mx1;
    r.w00 = pk2(f00, f00); r.w01 = pk2(f01, f01);
    r.w10 = pk2(f10, f10); r.w11 = pk2(f11, f11);
    r.o00 = cy0 * 128 + cx0; r.o01 = cy0 * 128 + cx1;
    r.o10 = cy1 * 128 + cx0; r.o11 = cy1 * 128 + cx1;
    return r;
}
__device__ __forceinline__ ull bil4(const ull* __restrict__ P, const Bil& b) {
    ull t = ffma2(b.w00, __ldg(P + b.o00), 0ULL);
    t = ffma2(b.w01, __ldg(P + b.o01), t);
    t = ffma2(b.w10, __ldg(P + b.o10), t);
    return ffma2(b.w11, __ldg(P + b.o11), t);
}

// ---------------- K3: streaming bilinear + low-rank mix, 2 px/thread ----------------
__global__ void __launch_bounds__(256) main_kernel() {
    __shared__ ull sB2[32][8][4];            // [cpair][k][pi] -> conflict-free
    __shared__ float sOff[8];
    int tid = threadIdx.x;
    int y = blockIdx.x;
    int j = y & 3;
    for (int t = tid; t < 1024; t += 256) {
        int i = t >> 5, k = (t >> 2) & 7, pi = t & 3;
        const float* Bp = g_B + (j * 4 + pi) * 512;
        sB2[i][k][pi] = pk2(Bp[(2 * i) * 8 + k], Bp[(2 * i + 1) * 8 + k]);
    }
    if (tid < 8) sOff[tid] = g_off[j * 8 + tid];
    __syncthreads();

    int xA = tid;            // pixel A
    int xB = tid + 256;      // pixel B (same phase: 256 % 4 == 0)
    int pi = tid & 3;
    int ph = j * 4 + pi;
    float offx = sOff[pi * 2 + 0];
    float offy = sOff[pi * 2 + 1];
    Bil bA = make_bil(xA, y, offx, offy);
    Bil bB = make_bil(xB, y, offx, offy);

    // mid for both pixels via AF bilinear
    ull mkA[8], mkB[8];
    const ull* AFp = g_AF2 + ph * 4 * 16384;
#pragma unroll
    for (int kp = 0; kp < 4; kp++) {
        const ull* Q = AFp + kp * 16384;
        ull a = bil4(Q, bA);
        ull b = bil4(Q, bB);
        float2 ma = upk2(a), mb = upk2(b);
        mkA[2 * kp] = pk2(ma.x, ma.x); mkA[2 * kp + 1] = pk2(ma.y, ma.y);
        mkB[2 * kp] = pk2(mb.x, mb.x); mkB[2 * kp + 1] = pk2(mb.y, mb.y);
    }

    // stream channel pairs: two independent gather+mix chains
    int baseA = y * 512 + xA;
    int baseB = y * 512 + xB;
#pragma unroll
    for (int i = 0; i < 32; i++) {
        const ull* F = (const ull*)g_feat2 + (i << 14);
        ull tA = bil4(F, bA);
        ull tB = bil4(F, bB);
#pragma unroll
        for (int k = 0; k < 8; k++) {
            ull bw = sB2[i][k][pi];
            tA = ffma2(bw, mkA[k], tA);
            tB = ffma2(bw, mkB[k], tB);
        }
        ((ull*)g_out2)[(i << 18) + baseA] = tA;
        ((ull*)g_out2)[(i << 18) + baseB] = tB;
    }
}

// ---------------- K4: tail conv3x3, 64->3 ch, 4-row streaming ----------------
__global__ void __launch_bounds__(256) tail_kernel(const float* __restrict__ tw,
                                                   const float* __restrict__ tb) {
    __shared__ __align__(16) ull sw2[3][32][9];     // packed (c0,c1) weights
    int tid = threadIdx.x;
    for (int i = tid; i < 864; i += 256) {
        int o = i / 288, rem = i % 288, p = rem / 9, t = rem % 9;
        sw2[o][p][t] = pk2(tw[o * 576 + (2 * p) * 9 + t],
                           tw[o * 576 + (2 * p + 1) * 9 + t]);
    }
    __syncthreads();

    int x = blockIdx.x * 256 + tid;
    int y0 = blockIdx.y * 4;
    bool xm = x > 0, xp = x < 511;
    ull acc[4][3];
#pragma unroll
    for (int oy = 0; oy < 4; oy++)
#pragma unroll
        for (int o = 0; o < 3; o++) acc[oy][o] = 0ULL;

    for (int pair = 0; pair < 32; pair++) {
        const ull* P = (const ull*)g_out2 + (pair << 18);
#pragma unroll
        for (int r = 0; r < 6; r++) {
            int yy = y0 - 1 + r;
            bool vy = (yy >= 0) && (yy < 512);
            int row = yy * 512 + x;
            ull v0 = (vy && xm) ? __ldg(P + row - 1) : 0ULL;
            ull v1 = vy ? __ldg(P + row) : 0ULL;
            ull v2 = (vy && xp) ? __ldg(P + row + 1) : 0ULL;
#pragma unroll
            for (int oy = 0; oy < 4; oy++) {
                int ky = r - oy;
                if (ky < 0 || ky > 2) continue;
#pragma unroll
                for (int o = 0; o < 3; o++) {
                    ull a = acc[oy][o];
                    a = ffma2(sw2[o][pair][ky * 3 + 0], v0, a);
                    a = ffma2(sw2[o][pair][ky * 3 + 1], v1, a);
                    a = ffma2(sw2[o][pair][ky * 3 + 2], v2, a);
                    acc[oy][o] = a;
                }
            }
        }
    }
#pragma unroll
    for (int oy = 0; oy < 4; oy++) {
        int row = (y0 + oy) * 512 + x;
        float2 a0 = upk2(acc[oy][0]);
        float2 a1 = upk2(acc[oy][1]);
        float2 a2 = upk2(acc[oy][2]);
        g_pred4[row] = make_float4(__ldg(tb + 0) + a0.x + a0.y,
                                   __ldg(tb + 1) + a1.x + a1.y,
                                   __ldg(tb + 2) + a2.x + a2.y, 0.f);
    }
}

// ---------------- K5: query gather ----------------
__global__ void gather_kernel(const float* __restrict__ coord,
                              const float* __restrict__ cell,
                              float* __restrict__ out) {
    int q = blockIdx.x * 256 + threadIdx.x;
    float2 cd = __ldg((const float2*)coord + q);
    float2 cl = __ldg((const float2*)cell + q);
    const float LO = -0.999999f, HI = 0.999999f;
    float gyq = fminf(fmaxf(cd.x - cl.x * 0.5f + 1e-6f, LO), HI);
    float gxq = fminf(fmaxf(cd.y - cl.y * 0.5f + 1e-6f, LO), HI);
    int xi = (int)rintf((gxq + 1.0f) * 0.5f * 511.0f);
    int yi = (int)rintf((gyq + 1.0f) * 0.5f * 511.0f);
    xi = min(511, max(0, xi));
    yi = min(511, max(0, yi));
    float4 v = __ldg(&g_pred4[(yi << 9) + xi]);
    out[q * 3 + 0] = v.x;
    out[q * 3 + 1] = v.y;
    out[q * 3 + 2] = v.z;
}

// ---------------- launch ----------------
extern "C" void kernel_launch(void* const* d_in, const int* in_sizes, int n_in,
                              void* d_out, int out_size) {
    const float* inp   = (const float*)d_in[0];
    const float* coord = (const float*)d_in[1];
    const float* cell  = (const float*)d_in[2];
    const float* enc_w = (const float*)d_in[3];
    const float* enc_b = (const float*)d_in[4];
    const float* w1    = (const float*)d_in[5];
    const float* b1    = (const float*)d_in[6];
    const float* w2    = (const float*)d_in[7];
    const float* b2    = (const float*)d_in[8];
    const float* rw    = (const float*)d_in[9];
    const float* rb    = (const float*)d_in[10];
    const float* ow    = (const float*)d_in[11];
    const float* ob    = (const float*)d_in[12];
    const float* tw    = (const float*)d_in[13];
    const float* tb    = (const float*)d_in[14];
    const float* wc    = (const float*)d_in[15];
    const float* we    = (const float*)d_in[16];
    float* out = (float*)d_out;

    enc_kernel<<<2048, 256>>>(inp, enc_w, enc_b);
    phase_kernel<<<16, 64>>>(w1, b1, w2, b2, rw, rb, ow, ob, wc, we);
    af_kernel<<<1024, 256>>>();
    main_kernel<<<512, 256>>>();
    tail_kernel<<<dim3(2, 128), 256>>>(tw, tb);
    gather_kernel<<<1024, 256>>>(coord, cell, out);
}